// round 1
// baseline (speedup 1.0000x reference)
#include <cuda_runtime.h>

#define Bz   4
#define Sz   4096
#define Hz   8
#define Lz   1024      // H * DI
#define N1z  384       // 3 * DO
#define NCH  32        // chunks over S
#define CLEN 128       // S / NCH
#define EPSf 1e-6f

// ---------------- scratch (static device memory; no allocations) ----------------
static __device__ float  g_csum_ln[(size_t)Bz * Sz * Lz];        // 64 MB
static __device__ float  g_h3[(size_t)Bz * Sz * Hz * N1z];       // 192 MB
static __device__ float2 g_fgi[(size_t)Bz * Sz * Lz];            // 128 MB (f, i) pairs
static __device__ float  g_cell[(size_t)Bz * Sz * Lz];           // 64 MB
static __device__ float  g_og[(size_t)Bz * Sz * Lz];             // 64 MB
static __device__ float  g_chA[Bz * NCH * Lz];                   // cumsum chunk sums/offsets
static __device__ float  g_chF[Bz * NCH * Lz];                   // scan chunk f-product
static __device__ float  g_chAcc[Bz * NCH * Lz];                 // scan chunk accumulation
static __device__ float  g_carry[Bz * NCH * Lz];                 // scan chunk carry-in

// =====================================================================
// Phase 1: exclusive cumsum over S + LayerNorm over (H,DI) per (b,s)
// =====================================================================
__global__ void k_scan1_partial(const float* __restrict__ x) {
    const int b = blockIdx.x, ch = blockIdx.y, l = threadIdx.x;
    const float* p = x + (size_t)(b * Sz + ch * CLEN) * Lz + l;
    float s0 = 0.f, s1 = 0.f, s2 = 0.f, s3 = 0.f;
    #pragma unroll 4
    for (int i = 0; i < CLEN; i += 4) {
        s0 += p[(size_t)(i + 0) * Lz];
        s1 += p[(size_t)(i + 1) * Lz];
        s2 += p[(size_t)(i + 2) * Lz];
        s3 += p[(size_t)(i + 3) * Lz];
    }
    g_chA[(b * NCH + ch) * Lz + l] = (s0 + s1) + (s2 + s3);
}

__global__ void k_scan1_offsets() {
    const int b = blockIdx.x, l = threadIdx.x;
    float run = 0.f;
    for (int ch = 0; ch < NCH; ch++) {
        const int idx = (b * NCH + ch) * Lz + l;
        const float t = g_chA[idx];
        g_chA[idx] = run;
        run += t;
    }
}

__global__ void k_scan1_ln(const float* __restrict__ x,
                           const float* __restrict__ gam,
                           const float* __restrict__ bet) {
    __shared__ float sred[64];
    __shared__ float s_stats[2];
    const int b = blockIdx.x, ch = blockIdx.y, l = threadIdx.x;
    const int wid = l >> 5, lane = l & 31;
    float c = g_chA[(b * NCH + ch) * Lz + l];
    const float gv = gam[l], bv = bet[l];
    const float* p = x + (size_t)(b * Sz + ch * CLEN) * Lz + l;
    float* o = g_csum_ln + (size_t)(b * Sz + ch * CLEN) * Lz + l;
    for (int i = 0; i < CLEN; i++) {
        const float v = c;
        float r1 = v, r2 = v * v;
        #pragma unroll
        for (int off = 16; off > 0; off >>= 1) {
            r1 += __shfl_down_sync(0xffffffffu, r1, off);
            r2 += __shfl_down_sync(0xffffffffu, r2, off);
        }
        if (lane == 0) { sred[wid] = r1; sred[32 + wid] = r2; }
        __syncthreads();
        if (wid == 0) {
            float t1 = sred[lane], t2 = sred[32 + lane];
            #pragma unroll
            for (int off = 16; off > 0; off >>= 1) {
                t1 += __shfl_down_sync(0xffffffffu, t1, off);
                t2 += __shfl_down_sync(0xffffffffu, t2, off);
            }
            if (lane == 0) {
                const float mu = t1 * (1.f / 1024.f);
                s_stats[0] = mu;
                s_stats[1] = rsqrtf(t2 * (1.f / 1024.f) - mu * mu + EPSf);
            }
        }
        __syncthreads();
        o[(size_t)i * Lz] = (v - s_stats[0]) * s_stats[1] * gv + bv;
        c += p[(size_t)i * Lz];
    }
}

// =====================================================================
// Batched per-head SGEMM: C[m,h,n] = [A0 | A1][m,h,:256] @ W[h] + bias[h]
// 128x128 tile, BK=8, 256 threads, 8x8 per thread, double-buffered smem
// =====================================================================
template <int NLD, bool PHASE1>
__global__ __launch_bounds__(256, 2) void k_gemm(const float* __restrict__ A0,
                                                 const float* __restrict__ W,
                                                 const float* __restrict__ bias) {
    const float* __restrict__ A1 = PHASE1 ? g_csum_ln : g_cell;
    float* __restrict__ C = PHASE1 ? g_h3 : g_og;

    const int mt = blockIdx.x, nt = blockIdx.y, h = blockIdx.z;
    const int tid = threadIdx.x;
    const int m0 = mt * 128, n0 = nt * 128;

    __shared__ float As[2][8][128];
    __shared__ float Bs[2][8][128];

    const int am = tid >> 1;            // 0..127 (row in A tile)
    const int ak = (tid & 1) * 4;       // 0 or 4 (k in A tile)
    const int bk = tid >> 5;            // 0..7   (k in B tile)
    const int bn = (tid & 31) * 4;      // 0..124 (n in B tile)

    const float* Wh = W + (size_t)h * 256 * NLD;
    const size_t arow = ((size_t)(m0 + am) * Hz + h) * 128;

    const int tr = (tid >> 4) * 8;
    const int tc = (tid & 15) * 8;

    float acc[8][8];
    #pragma unroll
    for (int i = 0; i < 8; i++)
        #pragma unroll
        for (int j = 0; j < 8; j++) acc[i][j] = 0.f;

    // prefetch k-tile 0 (always from A0)
    {
        float4 a4 = *(const float4*)(A0 + arow + ak);
        float4 b4 = *(const float4*)(Wh + (size_t)bk * NLD + n0 + bn);
        As[0][ak + 0][am] = a4.x;
        As[0][ak + 1][am] = a4.y;
        As[0][ak + 2][am] = a4.z;
        As[0][ak + 3][am] = a4.w;
        *(float4*)(&Bs[0][bk][bn]) = b4;
    }
    __syncthreads();

    #pragma unroll 1
    for (int kt = 0; kt < 32; kt++) {
        const int cur = kt & 1;
        float4 na4, nb4;
        if (kt < 31) {
            const int k2 = kt + 1;
            const float* Asrc = (k2 < 16) ? A0 : A1;
            const int koff = (k2 & 15) * 8;
            na4 = *(const float4*)(Asrc + arow + koff + ak);
            nb4 = *(const float4*)(Wh + (size_t)(k2 * 8 + bk) * NLD + n0 + bn);
        }
        #pragma unroll
        for (int kk = 0; kk < 8; kk++) {
            float a[8], bb[8];
            *(float4*)(a)      = *(const float4*)(&As[cur][kk][tr]);
            *(float4*)(a + 4)  = *(const float4*)(&As[cur][kk][tr + 4]);
            *(float4*)(bb)     = *(const float4*)(&Bs[cur][kk][tc]);
            *(float4*)(bb + 4) = *(const float4*)(&Bs[cur][kk][tc + 4]);
            #pragma unroll
            for (int i = 0; i < 8; i++)
                #pragma unroll
                for (int j = 0; j < 8; j++)
                    acc[i][j] = fmaf(a[i], bb[j], acc[i][j]);
        }
        if (kt < 31) {
            const int nxt = cur ^ 1;
            As[nxt][ak + 0][am] = na4.x;
            As[nxt][ak + 1][am] = na4.y;
            As[nxt][ak + 2][am] = na4.z;
            As[nxt][ak + 3][am] = na4.w;
            *(float4*)(&Bs[nxt][bk][bn]) = nb4;
            __syncthreads();
        }
    }

    float bv[8];
    *(float4*)(bv)     = *(const float4*)(bias + h * NLD + n0 + tc);
    *(float4*)(bv + 4) = *(const float4*)(bias + h * NLD + n0 + tc + 4);
    #pragma unroll
    for (int i = 0; i < 8; i++) {
        const size_t crow = ((size_t)(m0 + tr + i) * Hz + h) * NLD + n0 + tc;
        float4 o1 = make_float4(acc[i][0] + bv[0], acc[i][1] + bv[1],
                                acc[i][2] + bv[2], acc[i][3] + bv[3]);
        float4 o2 = make_float4(acc[i][4] + bv[4], acc[i][5] + bv[5],
                                acc[i][6] + bv[6], acc[i][7] + bv[7]);
        *(float4*)(C + crow)     = o1;
        *(float4*)(C + crow + 4) = o2;
    }
}

// =====================================================================
// Phase 3: LN over (H,3,DO) per (b,s), gates, per-chunk scan composition
// =====================================================================
__global__ void k_gates(const float* __restrict__ gam, const float* __restrict__ bet) {
    __shared__ float row[3072];
    __shared__ float sred[64];
    __shared__ float s_stats[2];
    const int b = blockIdx.x, ch = blockIdx.y, l = threadIdx.x;
    const int wid = l >> 5, lane = l & 31;
    const int h = l >> 7, dd = l & 127;
    const int pb = (h * 3) * 128 + dd;
    const float gi = gam[pb], gf = gam[pb + 128], gh = gam[pb + 256];
    const float bi = bet[pb], bf = bet[pb + 128], bh = bet[pb + 256];
    float F = 1.f, Acc = 0.f;
    for (int i = 0; i < CLEN; i++) {
        const size_t rb = (size_t)(b * Sz + ch * CLEN + i) * (Hz * N1z);
        const float v0 = g_h3[rb + l];
        const float v1 = g_h3[rb + 1024 + l];
        const float v2 = g_h3[rb + 2048 + l];
        row[l] = v0; row[1024 + l] = v1; row[2048 + l] = v2;
        float r1 = v0 + v1 + v2;
        float r2 = v0 * v0 + v1 * v1 + v2 * v2;
        #pragma unroll
        for (int off = 16; off > 0; off >>= 1) {
            r1 += __shfl_down_sync(0xffffffffu, r1, off);
            r2 += __shfl_down_sync(0xffffffffu, r2, off);
        }
        if (lane == 0) { sred[wid] = r1; sred[32 + wid] = r2; }
        __syncthreads();
        if (wid == 0) {
            float t1 = sred[lane], t2 = sred[32 + lane];
            #pragma unroll
            for (int off = 16; off > 0; off >>= 1) {
                t1 += __shfl_down_sync(0xffffffffu, t1, off);
                t2 += __shfl_down_sync(0xffffffffu, t2, off);
            }
            if (lane == 0) {
                const float mu = t1 * (1.f / 3072.f);
                s_stats[0] = mu;
                s_stats[1] = rsqrtf(t2 * (1.f / 3072.f) - mu * mu + EPSf);
            }
        }
        __syncthreads();
        const float mu = s_stats[0], rs = s_stats[1];
        const int base = h * N1z + dd;
        const float xig = (row[base]       - mu) * rs * gi + bi;
        const float xfg = (row[base + 128] - mu) * rs * gf + bf;
        const float xhd = (row[base + 256] - mu) * rs * gh + bh;
        const float f  = 1.f / (1.f + __expf(-xfg));
        const float ii = (1.f / (1.f + __expf(-xig))) * fmaxf(xhd, 0.f);
        g_fgi[(size_t)(b * Sz + ch * CLEN + i) * Lz + l] = make_float2(f, ii);
        Acc = f * Acc + ii;
        F *= f;
        __syncthreads();
    }
    const int ci = (b * NCH + ch) * Lz + l;
    g_chF[ci] = F;
    g_chAcc[ci] = Acc;
}

__global__ void k_carry(const float* __restrict__ init_cx) {
    const int b = blockIdx.x, l = threadIdx.x;
    float c = init_cx[l];
    for (int ch = 0; ch < NCH; ch++) {
        const int idx = (b * NCH + ch) * Lz + l;
        g_carry[idx] = c;
        c = g_chF[idx] * c + g_chAcc[idx];
    }
}

__global__ void k_replay() {
    const int b = blockIdx.x, ch = blockIdx.y, l = threadIdx.x;
    float c = g_carry[(b * NCH + ch) * Lz + l];
    const size_t base = (size_t)(b * Sz + ch * CLEN) * Lz + l;
    #pragma unroll 4
    for (int i = 0; i < CLEN; i++) {
        const float2 fi = g_fgi[base + (size_t)i * Lz];
        c = fi.x * c + fi.y;
        g_cell[base + (size_t)i * Lz] = c;
    }
}

// =====================================================================
// Phase 5: LN over (H,DO) per (b,s), sigmoid(og) * cell -> out
// =====================================================================
__global__ void k_final(const float* __restrict__ gam, const float* __restrict__ bet,
                        float* __restrict__ out) {
    __shared__ float sred[16];
    __shared__ float s_stats[2];
    const int bs = blockIdx.x, t = threadIdx.x;
    const int wid = t >> 5, lane = t & 31;
    const size_t base = (size_t)bs * Lz + t * 4;
    const float4 v = *(const float4*)(g_og + base);
    float r1 = v.x + v.y + v.z + v.w;
    float r2 = v.x * v.x + v.y * v.y + v.z * v.z + v.w * v.w;
    #pragma unroll
    for (int off = 16; off > 0; off >>= 1) {
        r1 += __shfl_down_sync(0xffffffffu, r1, off);
        r2 += __shfl_down_sync(0xffffffffu, r2, off);
    }
    if (lane == 0) { sred[wid] = r1; sred[8 + wid] = r2; }
    __syncthreads();
    if (wid == 0) {
        float t1 = lane < 8 ? sred[lane] : 0.f;
        float t2 = lane < 8 ? sred[8 + lane] : 0.f;
        #pragma unroll
        for (int off = 4; off > 0; off >>= 1) {
            t1 += __shfl_down_sync(0xffffffffu, t1, off);
            t2 += __shfl_down_sync(0xffffffffu, t2, off);
        }
        if (lane == 0) {
            const float mu = t1 * (1.f / 1024.f);
            s_stats[0] = mu;
            s_stats[1] = rsqrtf(t2 * (1.f / 1024.f) - mu * mu + EPSf);
        }
    }
    __syncthreads();
    const float mu = s_stats[0], rs = s_stats[1];
    const float4 cc = *(const float4*)(g_cell + base);
    const float4 gg = *(const float4*)(gam + t * 4);
    const float4 bb = *(const float4*)(bet + t * 4);
    float4 o;
    o.x = cc.x / (1.f + __expf(-((v.x - mu) * rs * gg.x + bb.x)));
    o.y = cc.y / (1.f + __expf(-((v.y - mu) * rs * gg.y + bb.y)));
    o.z = cc.z / (1.f + __expf(-((v.z - mu) * rs * gg.z + bb.z)));
    o.w = cc.w / (1.f + __expf(-((v.w - mu) * rs * gg.w + bb.w)));
    *(float4*)(out + base) = o;
}

// =====================================================================
extern "C" void kernel_launch(void* const* d_in, const int* in_sizes, int n_in,
                              void* d_out, int out_size) {
    (void)in_sizes; (void)n_in; (void)out_size;
    const float* x       = (const float*)d_in[0];
    const float* W_hid   = (const float*)d_in[1];
    const float* b_hid   = (const float*)d_in[2];
    const float* g_cs    = (const float*)d_in[3];
    const float* be_cs   = (const float*)d_in[4];
    const float* g_hd    = (const float*)d_in[5];
    const float* be_hd   = (const float*)d_in[6];
    const float* W_og    = (const float*)d_in[7];
    const float* b_og    = (const float*)d_in[8];
    const float* g_ogp   = (const float*)d_in[9];
    const float* be_ogp  = (const float*)d_in[10];
    const float* init_cx = (const float*)d_in[11];
    float* out = (float*)d_out;

    // Phase 1: exclusive cumsum + LN(csum)
    k_scan1_partial<<<dim3(Bz, NCH), 1024>>>(x);
    k_scan1_offsets<<<Bz, 1024>>>();
    k_scan1_ln<<<dim3(Bz, NCH), 1024>>>(x, g_cs, be_cs);

    // Phase 2: h3 = [x | ln(csum)] @ W_hid + b_hid
    k_gemm<N1z, true><<<dim3(Sz * Bz / 128, N1z / 128, Hz), 256>>>(x, W_hid, b_hid);

    // Phase 3: LN(h3), gates, chunk compositions
    k_gates<<<dim3(Bz, NCH), 1024>>>(g_hd, be_hd);

    // Phase 4: recurrent scan c = f*c + i
    k_carry<<<Bz, 1024>>>(init_cx);
    k_replay<<<dim3(Bz, NCH), 1024>>>();

    // Phase 5: og = [x | cell] @ W_og + b_og, LN, sigmoid*cell
    k_gemm<128, false><<<dim3(Sz * Bz / 128, 1, Hz), 256>>>(x, W_og, b_og);
    k_final<<<Bz * Sz, 256>>>(g_ogp, be_ogp, out);
}

// round 2
// speedup vs baseline: 1.0008x; 1.0008x over previous
#include <cuda_runtime.h>

#define Bz   4
#define Sz   4096
#define Hz   8
#define Lz   1024      // H * DI
#define N1z  384       // 3 * DO
#define NCH  32        // chunks over S
#define CLEN 128       // S / NCH
#define EPSf 1e-6f

// ---------------- scratch (static device memory; no allocations) ----------------
static __device__ float  g_csum_ln[(size_t)Bz * Sz * Lz];        // 64 MB
static __device__ float  g_h3[(size_t)Bz * Sz * Hz * N1z];       // 192 MB
static __device__ float2 g_fgi[(size_t)Bz * Sz * Lz];            // 128 MB (f, i) pairs
static __device__ float  g_cell[(size_t)Bz * Sz * Lz];           // 64 MB
static __device__ float  g_og[(size_t)Bz * Sz * Lz];             // 64 MB
static __device__ float  g_chA[Bz * NCH * Lz];                   // cumsum chunk sums/offsets
static __device__ float  g_chF[Bz * NCH * Lz];                   // scan chunk f-product
static __device__ float  g_chAcc[Bz * NCH * Lz];                 // scan chunk accumulation
static __device__ float  g_carry[Bz * NCH * Lz];                 // scan chunk carry-in

// =====================================================================
// Phase 1: exclusive cumsum over S + LayerNorm over (H,DI) per (b,s)
// =====================================================================
__global__ void k_scan1_partial(const float* __restrict__ x) {
    const int b = blockIdx.x, ch = blockIdx.y, l = threadIdx.x;
    const float* p = x + (size_t)(b * Sz + ch * CLEN) * Lz + l;
    float s0 = 0.f, s1 = 0.f, s2 = 0.f, s3 = 0.f;
    #pragma unroll 4
    for (int i = 0; i < CLEN; i += 4) {
        s0 += p[(size_t)(i + 0) * Lz];
        s1 += p[(size_t)(i + 1) * Lz];
        s2 += p[(size_t)(i + 2) * Lz];
        s3 += p[(size_t)(i + 3) * Lz];
    }
    g_chA[(b * NCH + ch) * Lz + l] = (s0 + s1) + (s2 + s3);
}

__global__ void k_scan1_offsets() {
    const int b = blockIdx.x, l = threadIdx.x;
    float run = 0.f;
    for (int ch = 0; ch < NCH; ch++) {
        const int idx = (b * NCH + ch) * Lz + l;
        const float t = g_chA[idx];
        g_chA[idx] = run;
        run += t;
    }
}

__global__ void k_scan1_ln(const float* __restrict__ x,
                           const float* __restrict__ gam,
                           const float* __restrict__ bet) {
    __shared__ float sred[64];
    __shared__ float s_stats[2];
    const int b = blockIdx.x, ch = blockIdx.y, l = threadIdx.x;
    const int wid = l >> 5, lane = l & 31;
    float c = g_chA[(b * NCH + ch) * Lz + l];
    const float gv = gam[l], bv = bet[l];
    const float* p = x + (size_t)(b * Sz + ch * CLEN) * Lz + l;
    float* o = g_csum_ln + (size_t)(b * Sz + ch * CLEN) * Lz + l;
    for (int i = 0; i < CLEN; i++) {
        const float v = c;
        float r1 = v, r2 = v * v;
        #pragma unroll
        for (int off = 16; off > 0; off >>= 1) {
            r1 += __shfl_down_sync(0xffffffffu, r1, off);
            r2 += __shfl_down_sync(0xffffffffu, r2, off);
        }
        if (lane == 0) { sred[wid] = r1; sred[32 + wid] = r2; }
        __syncthreads();
        if (wid == 0) {
            float t1 = sred[lane], t2 = sred[32 + lane];
            #pragma unroll
            for (int off = 16; off > 0; off >>= 1) {
                t1 += __shfl_down_sync(0xffffffffu, t1, off);
                t2 += __shfl_down_sync(0xffffffffu, t2, off);
            }
            if (lane == 0) {
                const float mu = t1 * (1.f / 1024.f);
                s_stats[0] = mu;
                s_stats[1] = rsqrtf(t2 * (1.f / 1024.f) - mu * mu + EPSf);
            }
        }
        __syncthreads();
        o[(size_t)i * Lz] = (v - s_stats[0]) * s_stats[1] * gv + bv;
        c += p[(size_t)i * Lz];
    }
}

// =====================================================================
// Batched per-head SGEMM: C[m,h,n] = [A0 | A1][m,h,:256] @ W[h] + bias[h]
// 128x128 tile, BK=8, 256 threads, 8x8 per thread, double-buffered smem
// =====================================================================
template <int NLD, bool PHASE1>
__global__ __launch_bounds__(256, 2) void k_gemm(const float* __restrict__ A0,
                                                 const float* __restrict__ W,
                                                 const float* __restrict__ bias) {
    const float* __restrict__ A1 = PHASE1 ? g_csum_ln : g_cell;
    float* __restrict__ C = PHASE1 ? g_h3 : g_og;

    const int mt = blockIdx.x, nt = blockIdx.y, h = blockIdx.z;
    const int tid = threadIdx.x;
    const int m0 = mt * 128, n0 = nt * 128;

    __shared__ float As[2][8][128];
    __shared__ float Bs[2][8][128];

    const int am = tid >> 1;            // 0..127 (row in A tile)
    const int ak = (tid & 1) * 4;       // 0 or 4 (k in A tile)
    const int bk = tid >> 5;            // 0..7   (k in B tile)
    const int bn = (tid & 31) * 4;      // 0..124 (n in B tile)

    const float* Wh = W + (size_t)h * 256 * NLD;
    const size_t arow = ((size_t)(m0 + am) * Hz + h) * 128;

    const int tr = (tid >> 4) * 8;
    const int tc = (tid & 15) * 8;

    float acc[8][8];
    #pragma unroll
    for (int i = 0; i < 8; i++)
        #pragma unroll
        for (int j = 0; j < 8; j++) acc[i][j] = 0.f;

    // prefetch k-tile 0 (always from A0)
    {
        float4 a4 = *(const float4*)(A0 + arow + ak);
        float4 b4 = *(const float4*)(Wh + (size_t)bk * NLD + n0 + bn);
        As[0][ak + 0][am] = a4.x;
        As[0][ak + 1][am] = a4.y;
        As[0][ak + 2][am] = a4.z;
        As[0][ak + 3][am] = a4.w;
        *(float4*)(&Bs[0][bk][bn]) = b4;
    }
    __syncthreads();

    #pragma unroll 1
    for (int kt = 0; kt < 32; kt++) {
        const int cur = kt & 1;
        float4 na4, nb4;
        if (kt < 31) {
            const int k2 = kt + 1;
            const float* Asrc = (k2 < 16) ? A0 : A1;
            const int koff = (k2 & 15) * 8;
            na4 = *(const float4*)(Asrc + arow + koff + ak);
            nb4 = *(const float4*)(Wh + (size_t)(k2 * 8 + bk) * NLD + n0 + bn);
        }
        #pragma unroll
        for (int kk = 0; kk < 8; kk++) {
            float a[8], bb[8];
            *(float4*)(a)      = *(const float4*)(&As[cur][kk][tr]);
            *(float4*)(a + 4)  = *(const float4*)(&As[cur][kk][tr + 4]);
            *(float4*)(bb)     = *(const float4*)(&Bs[cur][kk][tc]);
            *(float4*)(bb + 4) = *(const float4*)(&Bs[cur][kk][tc + 4]);
            #pragma unroll
            for (int i = 0; i < 8; i++)
                #pragma unroll
                for (int j = 0; j < 8; j++)
                    acc[i][j] = fmaf(a[i], bb[j], acc[i][j]);
        }
        if (kt < 31) {
            const int nxt = cur ^ 1;
            As[nxt][ak + 0][am] = na4.x;
            As[nxt][ak + 1][am] = na4.y;
            As[nxt][ak + 2][am] = na4.z;
            As[nxt][ak + 3][am] = na4.w;
            *(float4*)(&Bs[nxt][bk][bn]) = nb4;
            __syncthreads();
        }
    }

    float bv[8];
    *(float4*)(bv)     = *(const float4*)(bias + h * NLD + n0 + tc);
    *(float4*)(bv + 4) = *(const float4*)(bias + h * NLD + n0 + tc + 4);
    #pragma unroll
    for (int i = 0; i < 8; i++) {
        const size_t crow = ((size_t)(m0 + tr + i) * Hz + h) * NLD + n0 + tc;
        float4 o1 = make_float4(acc[i][0] + bv[0], acc[i][1] + bv[1],
                                acc[i][2] + bv[2], acc[i][3] + bv[3]);
        float4 o2 = make_float4(acc[i][4] + bv[4], acc[i][5] + bv[5],
                                acc[i][6] + bv[6], acc[i][7] + bv[7]);
        *(float4*)(C + crow)     = o1;
        *(float4*)(C + crow + 4) = o2;
    }
}

// =====================================================================
// Phase 3: LN over (H,3,DO) per (b,s), gates, per-chunk scan composition
// =====================================================================
__global__ void k_gates(const float* __restrict__ gam, const float* __restrict__ bet) {
    __shared__ float row[3072];
    __shared__ float sred[64];
    __shared__ float s_stats[2];
    const int b = blockIdx.x, ch = blockIdx.y, l = threadIdx.x;
    const int wid = l >> 5, lane = l & 31;
    const int h = l >> 7, dd = l & 127;
    const int pb = (h * 3) * 128 + dd;
    const float gi = gam[pb], gf = gam[pb + 128], gh = gam[pb + 256];
    const float bi = bet[pb], bf = bet[pb + 128], bh = bet[pb + 256];
    float F = 1.f, Acc = 0.f;
    for (int i = 0; i < CLEN; i++) {
        const size_t rb = (size_t)(b * Sz + ch * CLEN + i) * (Hz * N1z);
        const float v0 = g_h3[rb + l];
        const float v1 = g_h3[rb + 1024 + l];
        const float v2 = g_h3[rb + 2048 + l];
        row[l] = v0; row[1024 + l] = v1; row[2048 + l] = v2;
        float r1 = v0 + v1 + v2;
        float r2 = v0 * v0 + v1 * v1 + v2 * v2;
        #pragma unroll
        for (int off = 16; off > 0; off >>= 1) {
            r1 += __shfl_down_sync(0xffffffffu, r1, off);
            r2 += __shfl_down_sync(0xffffffffu, r2, off);
        }
        if (lane == 0) { sred[wid] = r1; sred[32 + wid] = r2; }
        __syncthreads();
        if (wid == 0) {
            float t1 = sred[lane], t2 = sred[32 + lane];
            #pragma unroll
            for (int off = 16; off > 0; off >>= 1) {
                t1 += __shfl_down_sync(0xffffffffu, t1, off);
                t2 += __shfl_down_sync(0xffffffffu, t2, off);
            }
            if (lane == 0) {
                const float mu = t1 * (1.f / 3072.f);
                s_stats[0] = mu;
                s_stats[1] = rsqrtf(t2 * (1.f / 3072.f) - mu * mu + EPSf);
            }
        }
        __syncthreads();
        const float mu = s_stats[0], rs = s_stats[1];
        const int base = h * N1z + dd;
        const float xig = (row[base]       - mu) * rs * gi + bi;
        const float xfg = (row[base + 128] - mu) * rs * gf + bf;
        const float xhd = (row[base + 256] - mu) * rs * gh + bh;
        const float f  = 1.f / (1.f + __expf(-xfg));
        const float ii = (1.f / (1.f + __expf(-xig))) * fmaxf(xhd, 0.f);
        g_fgi[(size_t)(b * Sz + ch * CLEN + i) * Lz + l] = make_float2(f, ii);
        Acc = f * Acc + ii;
        F *= f;
        __syncthreads();
    }
    const int ci = (b * NCH + ch) * Lz + l;
    g_chF[ci] = F;
    g_chAcc[ci] = Acc;
}

__global__ void k_carry(const float* __restrict__ init_cx) {
    const int b = blockIdx.x, l = threadIdx.x;
    float c = init_cx[l];
    for (int ch = 0; ch < NCH; ch++) {
        const int idx = (b * NCH + ch) * Lz + l;
        g_carry[idx] = c;
        c = g_chF[idx] * c + g_chAcc[idx];
    }
}

__global__ void k_replay() {
    const int b = blockIdx.x, ch = blockIdx.y, l = threadIdx.x;
    float c = g_carry[(b * NCH + ch) * Lz + l];
    const size_t base = (size_t)(b * Sz + ch * CLEN) * Lz + l;
    #pragma unroll 4
    for (int i = 0; i < CLEN; i++) {
        const float2 fi = g_fgi[base + (size_t)i * Lz];
        c = fi.x * c + fi.y;
        g_cell[base + (size_t)i * Lz] = c;
    }
}

// =====================================================================
// Phase 5: LN over (H,DO) per (b,s), sigmoid(og) * cell -> out
// =====================================================================
__global__ void k_final(const float* __restrict__ gam, const float* __restrict__ bet,
                        float* __restrict__ out) {
    __shared__ float sred[16];
    __shared__ float s_stats[2];
    const int bs = blockIdx.x, t = threadIdx.x;
    const int wid = t >> 5, lane = t & 31;
    const size_t base = (size_t)bs * Lz + t * 4;
    const float4 v = *(const float4*)(g_og + base);
    float r1 = v.x + v.y + v.z + v.w;
    float r2 = v.x * v.x + v.y * v.y + v.z * v.z + v.w * v.w;
    #pragma unroll
    for (int off = 16; off > 0; off >>= 1) {
        r1 += __shfl_down_sync(0xffffffffu, r1, off);
        r2 += __shfl_down_sync(0xffffffffu, r2, off);
    }
    if (lane == 0) { sred[wid] = r1; sred[8 + wid] = r2; }
    __syncthreads();
    if (wid == 0) {
        float t1 = lane < 8 ? sred[lane] : 0.f;
        float t2 = lane < 8 ? sred[8 + lane] : 0.f;
        #pragma unroll
        for (int off = 4; off > 0; off >>= 1) {
            t1 += __shfl_down_sync(0xffffffffu, t1, off);
            t2 += __shfl_down_sync(0xffffffffu, t2, off);
        }
        if (lane == 0) {
            const float mu = t1 * (1.f / 1024.f);
            s_stats[0] = mu;
            s_stats[1] = rsqrtf(t2 * (1.f / 1024.f) - mu * mu + EPSf);
        }
    }
    __syncthreads();
    const float mu = s_stats[0], rs = s_stats[1];
    const float4 cc = *(const float4*)(g_cell + base);
    const float4 gg = *(const float4*)(gam + t * 4);
    const float4 bb = *(const float4*)(bet + t * 4);
    float4 o;
    o.x = cc.x / (1.f + __expf(-((v.x - mu) * rs * gg.x + bb.x)));
    o.y = cc.y / (1.f + __expf(-((v.y - mu) * rs * gg.y + bb.y)));
    o.z = cc.z / (1.f + __expf(-((v.z - mu) * rs * gg.z + bb.z)));
    o.w = cc.w / (1.f + __expf(-((v.w - mu) * rs * gg.w + bb.w)));
    *(float4*)(out + base) = o;
}

// =====================================================================
extern "C" void kernel_launch(void* const* d_in, const int* in_sizes, int n_in,
                              void* d_out, int out_size) {
    (void)in_sizes; (void)n_in; (void)out_size;
    const float* x       = (const float*)d_in[0];
    const float* W_hid   = (const float*)d_in[1];
    const float* b_hid   = (const float*)d_in[2];
    const float* g_cs    = (const float*)d_in[3];
    const float* be_cs   = (const float*)d_in[4];
    const float* g_hd    = (const float*)d_in[5];
    const float* be_hd   = (const float*)d_in[6];
    const float* W_og    = (const float*)d_in[7];
    const float* b_og    = (const float*)d_in[8];
    const float* g_ogp   = (const float*)d_in[9];
    const float* be_ogp  = (const float*)d_in[10];
    const float* init_cx = (const float*)d_in[11];
    float* out = (float*)d_out;

    // Phase 1: exclusive cumsum + LN(csum)
    k_scan1_partial<<<dim3(Bz, NCH), 1024>>>(x);
    k_scan1_offsets<<<Bz, 1024>>>();
    k_scan1_ln<<<dim3(Bz, NCH), 1024>>>(x, g_cs, be_cs);

    // Phase 2: h3 = [x | ln(csum)] @ W_hid + b_hid
    k_gemm<N1z, true><<<dim3(Sz * Bz / 128, N1z / 128, Hz), 256>>>(x, W_hid, b_hid);

    // Phase 3: LN(h3), gates, chunk compositions
    k_gates<<<dim3(Bz, NCH), 1024>>>(g_hd, be_hd);

    // Phase 4: recurrent scan c = f*c + i
    k_carry<<<Bz, 1024>>>(init_cx);
    k_replay<<<dim3(Bz, NCH), 1024>>>();

    // Phase 5: og = [x | cell] @ W_og + b_og, LN, sigmoid*cell
    k_gemm<128, false><<<dim3(Sz * Bz / 128, 1, Hz), 256>>>(x, W_og, b_og);
    k_final<<<Bz * Sz, 256>>>(g_ogp, be_ogp, out);
}